// round 16
// baseline (speedup 1.0000x reference)
#include <cuda_runtime.h>
#include <cuda_bf16.h>
#include <math.h>
#include <stdint.h>

#define NROWS 16384
#define CDIM  512
#define DDIM  2048

#define BN 64
#define BK 32                    // k elements per pipeline stage
#define STAGES 3

// Swizzled smem layout: two logical 64B rows per 128B physical row.
// phys(row, seg) = (row>>1)*128 + ((((row&1)<<2)|seg) ^ ((row>>1)&7))*16
// Conflict-free for cp.async 16B writes and ldmatrix m8n8 reads.
__device__ __forceinline__ uint32_t swz(int row, int seg) {
    return (uint32_t)((row >> 1) * 128 +
                      (((((row & 1) << 2) | seg) ^ ((row >> 1) & 7)) << 4));
}

// ---------------------------------------------------------------------------
// Static scratch (no allocation allowed). Activations stored as bf16 hi/lo
// plane pairs; value = hi + lo reconstructs fp32 to ~2^-18.
// ---------------------------------------------------------------------------
__device__ __nv_bfloat16 g_xh [(size_t)NROWS * CDIM], g_xl [(size_t)NROWS * CDIM];
__device__ __nv_bfloat16 g_rh [(size_t)NROWS * CDIM], g_rl [(size_t)NROWS * CDIM];
__device__ __nv_bfloat16 g_cAh[(size_t)NROWS * DDIM], g_cAl[(size_t)NROWS * DDIM];
__device__ __nv_bfloat16 g_cBh[(size_t)NROWS * DDIM], g_cBl[(size_t)NROWS * DDIM];
__device__ __nv_bfloat16 g_Wh [(size_t)DDIM * CDIM],  g_Wl [(size_t)DDIM * CDIM];
__device__ __nv_bfloat16 g_Wth[(size_t)CDIM * DDIM],  g_Wtl[(size_t)CDIM * DDIM];

// ---------------------------------------------------------------------------
// PTX helpers (family-common sm_80+: cp.async, mma.sync, ldmatrix)
// ---------------------------------------------------------------------------
__device__ __forceinline__ uint32_t smem_u32(const void* p) {
    return (uint32_t)__cvta_generic_to_shared(p);
}
__device__ __forceinline__ void cp16(uint32_t saddr, const void* gaddr) {
    asm volatile("cp.async.cg.shared.global [%0], [%1], 16;"
                 :: "r"(saddr), "l"(gaddr) : "memory");
}
__device__ __forceinline__ void cp_commit() {
    asm volatile("cp.async.commit_group;" ::: "memory");
}
#define CP_WAIT_GROUP(n) asm volatile("cp.async.wait_group %0;" :: "n"(n) : "memory")

__device__ __forceinline__ void ldsm_x4(uint32_t& r0, uint32_t& r1, uint32_t& r2,
                                        uint32_t& r3, uint32_t addr) {
    asm volatile("ldmatrix.sync.aligned.m8n8.x4.shared.b16 {%0,%1,%2,%3}, [%4];"
                 : "=r"(r0), "=r"(r1), "=r"(r2), "=r"(r3) : "r"(addr));
}
__device__ __forceinline__ void mma_bf16(float* c, const uint32_t* a,
                                         uint32_t b0, uint32_t b1) {
    asm("mma.sync.aligned.m16n8k16.row.col.f32.bf16.bf16.f32 "
        "{%0,%1,%2,%3}, {%4,%5,%6,%7}, {%8,%9}, {%0,%1,%2,%3};"
        : "+f"(c[0]), "+f"(c[1]), "+f"(c[2]), "+f"(c[3])
        : "r"(a[0]), "r"(a[1]), "r"(a[2]), "r"(a[3]), "r"(b0), "r"(b1));
}
__device__ __forceinline__ void split_bf16(float v, __nv_bfloat16& h, __nv_bfloat16& l) {
    h = __float2bfloat16(v);
    l = __float2bfloat16(v - __bfloat162float(h));
}

// ---------------------------------------------------------------------------
// Small kernels
// ---------------------------------------------------------------------------
__global__ void zero_losses_kernel(float* rl, float* cl) { *rl = 0.0f; *cl = 0.0f; }

__global__ void prep_w_kernel(const float* __restrict__ W) {
    int i = blockIdx.x * blockDim.x + threadIdx.x;
    if (i < DDIM * CDIM) {
        __nv_bfloat16 h, l;
        split_bf16(W[i], h, l);
        g_Wh[i] = h; g_Wl[i] = l;
        int d = i / CDIM, c = i % CDIM;
        g_Wth[(size_t)c * DDIM + d] = h;
        g_Wtl[(size_t)c * DDIM + d] = l;
    }
}
__global__ void prep_x_kernel(const float* __restrict__ X) {
    int i = blockIdx.x * blockDim.x + threadIdx.x;
    if (i < NROWS * CDIM) {
        __nv_bfloat16 h, l;
        split_bf16(X[i], h, l);
        g_xh[i] = h; g_xl[i] = l;
    }
}

// ---------------------------------------------------------------------------
// Unified bf16-split GEMM (mma.sync m16n8k16, 3-product hi/lo, ldmatrix,
// swizzled smem, 3-stage cp.async pipeline), templated on BM:
//   BM=128: 256 thr, 4x2 warps (step GEMM, big grid)
//   BM=64 : 128 thr, 2x2 warps (residual GEMM: 2x grid -> less wave-tail waste)
// + fused FISTA epilogue.  D = (Ah+Al)[NROWS x K] @ (Bh+Bl)[Ntot x K]^T
// ---------------------------------------------------------------------------
template <int BM_>
__global__ __launch_bounds__(BM_ * 2, 768 / (BM_ * 2))
void fista_mma_kernel(const __nv_bfloat16* __restrict__ Ah, const __nv_bfloat16* __restrict__ Al,
                      const __nv_bfloat16* __restrict__ Bh, const __nv_bfloat16* __restrict__ Bl,
                      int K, int nChunks, int Ntot, int mode,
                      const __nv_bfloat16* __restrict__ cInH, const __nv_bfloat16* __restrict__ cInL,
                      const __nv_bfloat16* __restrict__ cPreH, const __nv_bfloat16* __restrict__ cPreL,
                      float alpha, float beta,
                      __nv_bfloat16* __restrict__ outH, __nv_bfloat16* __restrict__ outL,
                      float* __restrict__ outF, float* __restrict__ out2,
                      const float* __restrict__ Xres, float* __restrict__ loss)
{
    constexpr int THREADS = BM_ * 2;
    constexpr int NWM = BM_ / 32;                      // warps along M
    constexpr int A_TILE = BM_ * 64;                   // bytes per A plane
    constexpr int B_TILE = 64 * 64;                    // bytes per B plane
    constexpr int STAGE_BYTES = 2 * A_TILE + 2 * B_TILE;

    extern __shared__ char dyn_smem[];
    __shared__ float s_red[THREADS];

    const int tid = threadIdx.x;
    const int lane = tid & 31, wid = tid >> 5;
    const int gq = lane >> 2, tig = lane & 3;
    const int warpM = wid % NWM, warpN = wid / NWM;    // NWM x 2 warps, 32x32 each
    const int rowBase = blockIdx.y * BM_;
    const int colBase = blockIdx.x * BN;
    const uint32_t sBase = smem_u32(dyn_smem);

    // Per-lane ldmatrix swizzled offsets (XOR term invariant under +16-row steps).
    const int aRowL = (lane & 7) + ((lane >> 3) & 1) * 8;
    const int aSegSel = (lane >> 4) & 1;
    const uint32_t aOff0 = swz(aRowL, 0 + aSegSel);     // ks=0: segs {0,1}
    const uint32_t aOff1 = swz(aRowL, 2 + aSegSel);     // ks=1: segs {2,3}
    const int bRowL = (lane & 7) + ((lane >> 4) & 1) * 8;
    const int bSegSel = (lane >> 3) & 1;
    const uint32_t bOff0 = swz(bRowL, 0 + bSegSel);
    const uint32_t bOff1 = swz(bRowL, 2 + bSegSel);

    float acc[2][4][4];                                 // [mi][ni(n8)][frag]
    #pragma unroll
    for (int mi = 0; mi < 2; mi++)
        #pragma unroll
        for (int ni = 0; ni < 4; ni++)
            #pragma unroll
            for (int q = 0; q < 4; q++) acc[mi][ni][q] = 0.0f;

    // ---- stage loader ----
    auto load_stage = [&](int t) {
        const uint32_t stB = sBase + (t % STAGES) * STAGE_BYTES;
        const int k0 = t * BK;
        #pragma unroll
        for (int p = 0; p < 2; p++) {                   // A planes: BM_*4 slots
            const __nv_bfloat16* base = p ? Al : Ah;
            #pragma unroll
            for (int i = 0; i < (BM_ * 4) / THREADS; i++) {
                int slot = tid + i * THREADS;
                int row = slot >> 2, seg = slot & 3;
                cp16(stB + p * A_TILE + swz(row, seg),
                     base + (size_t)(rowBase + row) * K + k0 + seg * 8);
            }
        }
        #pragma unroll
        for (int p = 0; p < 2; p++) {                   // B planes: 256 slots
            const __nv_bfloat16* base = p ? Bl : Bh;
            #pragma unroll
            for (int i = 0; i < 256 / THREADS; i++) {
                int slot = tid + i * THREADS;
                int row = slot >> 2, seg = slot & 3;
                cp16(stB + 2 * A_TILE + p * B_TILE + swz(row, seg),
                     base + (size_t)(colBase + row) * K + k0 + seg * 8);
            }
        }
    };

    // ---- prologue: two stages in flight ----
    load_stage(0); cp_commit();
    load_stage(1); cp_commit();

    // ---- mainloop ----
    for (int t = 0; t < nChunks; t++) {
        CP_WAIT_GROUP(1);                               // chunk t resident; t+1 may fly
        __syncthreads();
        const int pf = t + 2;
        if (pf < nChunks) load_stage(pf);
        cp_commit();

        const uint32_t stB = sBase + (t % STAGES) * STAGE_BYTES;
        const uint32_t aH = stB + (uint32_t)warpM * 2048;            // 32 rows = 2048B
        const uint32_t aL = aH + A_TILE;
        const uint32_t bH = stB + 2 * A_TILE + (uint32_t)warpN * 2048;
        const uint32_t bL = bH + B_TILE;

        #pragma unroll
        for (int ks = 0; ks < 2; ks++) {                // two k16 steps per BK=32
            const uint32_t aOff = ks ? aOff1 : aOff0;
            const uint32_t bOff = ks ? bOff1 : bOff0;
            uint32_t ah[2][4], al[2][4];
            #pragma unroll
            for (int mi = 0; mi < 2; mi++) {
                ldsm_x4(ah[mi][0], ah[mi][1], ah[mi][2], ah[mi][3], aH + aOff + mi * 1024);
                ldsm_x4(al[mi][0], al[mi][1], al[mi][2], al[mi][3], aL + aOff + mi * 1024);
            }
            #pragma unroll
            for (int np = 0; np < 2; np++) {            // n8 pair {2np, 2np+1}
                uint32_t bh0, bh1, bh2, bh3, bl0, bl1, bl2, bl3;
                ldsm_x4(bh0, bh1, bh2, bh3, bH + bOff + np * 1024);
                ldsm_x4(bl0, bl1, bl2, bl3, bL + bOff + np * 1024);
                #pragma unroll
                for (int mi = 0; mi < 2; mi++) {
                    mma_bf16(acc[mi][2 * np],     ah[mi], bh0, bh1);   // hi*hi
                    mma_bf16(acc[mi][2 * np],     ah[mi], bl0, bl1);   // hi*lo
                    mma_bf16(acc[mi][2 * np],     al[mi], bh0, bh1);   // lo*hi
                    mma_bf16(acc[mi][2 * np + 1], ah[mi], bh2, bh3);
                    mma_bf16(acc[mi][2 * np + 1], ah[mi], bl2, bl3);
                    mma_bf16(acc[mi][2 * np + 1], al[mi], bh2, bh3);
                }
            }
        }
    }

    // ---- fused epilogue ----
    float lsum = 0.0f;
    #pragma unroll
    for (int mi = 0; mi < 2; mi++) {
        #pragma unroll
        for (int ni = 0; ni < 4; ni++) {
            const int col = colBase + warpN * 32 + ni * 8 + 2 * tig;
            #pragma unroll
            for (int half = 0; half < 2; half++) {
                const int row = rowBase + warpM * 32 + mi * 16 + gq + half * 8;
                const float v0 = acc[mi][ni][half * 2 + 0];
                const float v1 = acc[mi][ni][half * 2 + 1];
                const size_t off = (size_t)row * Ntot + col;

                if (mode == 0) {
                    float w0 = fmaf(0.1f, v0, -0.01f);
                    float w1 = fmaf(0.1f, v1, -0.01f);
                    if (cInH) {
                        __nv_bfloat162 ch = *(const __nv_bfloat162*)(cInH + off);
                        __nv_bfloat162 cl = *(const __nv_bfloat162*)(cInL + off);
                        w0 = fmaf(alpha, __bfloat162float(ch.x) + __bfloat162float(cl.x), w0);
                        w1 = fmaf(alpha, __bfloat162float(ch.y) + __bfloat162float(cl.y), w1);
                        if (beta != 0.0f) {
                            __nv_bfloat162 ph = *(const __nv_bfloat162*)(cPreH + off);
                            __nv_bfloat162 pl = *(const __nv_bfloat162*)(cPreL + off);
                            w0 = fmaf(beta, __bfloat162float(ph.x) + __bfloat162float(pl.x), w0);
                            w1 = fmaf(beta, __bfloat162float(ph.y) + __bfloat162float(pl.y), w1);
                        }
                    }
                    w0 = fmaxf(w0, 0.0f);
                    w1 = fmaxf(w1, 0.0f);
                    lsum += w0 + w1;
                    __nv_bfloat16 h0, l0, h1, l1;
                    split_bf16(w0, h0, l0);
                    split_bf16(w1, h1, l1);
                    *(__nv_bfloat162*)(outH + off) = __nv_bfloat162(h0, h1);
                    *(__nv_bfloat162*)(outL + off) = __nv_bfloat162(l0, l1);
                    if (outF) *(float2*)(outF + off) = make_float2(w0, w1);
                } else {
                    float2 xv = *(const float2*)(Xres + off);
                    float r0 = xv.x - v0, r1 = xv.y - v1;
                    lsum = fmaf(r0, r0, fmaf(r1, r1, lsum));
                    if (outH) {
                        __nv_bfloat16 h0, l0, h1, l1;
                        split_bf16(r0, h0, l0);
                        split_bf16(r1, h1, l1);
                        *(__nv_bfloat162*)(outH + off) = __nv_bfloat162(h0, h1);
                        *(__nv_bfloat162*)(outL + off) = __nv_bfloat162(l0, l1);
                    }
                    if (out2) *(float2*)(out2 + off) = make_float2(v0, v1);
                    if (outF) *(float2*)(outF + off) = make_float2(r0, r1);
                }
            }
        }
    }

    if (loss) {
        s_red[tid] = lsum;
        __syncthreads();
        #pragma unroll
        for (int s = THREADS / 2; s > 0; s >>= 1) {
            if (tid < s) s_red[tid] += s_red[tid + s];
            __syncthreads();
        }
        if (tid == 0) atomicAdd(loss, (mode == 0 ? 0.1f : 1.0f) * s_red[0]);
    }
}

// ---------------------------------------------------------------------------
extern "C" void kernel_launch(void* const* d_in, const int* in_sizes, int n_in,
                              void* d_out, int out_size)
{
    (void)in_sizes; (void)n_in; (void)out_size;
    const float* x = (const float*)d_in[0];       // [16384, 512]
    const float* W = (const float*)d_in[1];       // [2048, 512]

    float* out    = (float*)d_out;
    float* out_c  = out;
    float* out_xp = out_c  + (size_t)NROWS * DDIM;
    float* out_r  = out_xp + (size_t)NROWS * CDIM;
    float* out_rl = out_r  + (size_t)NROWS * CDIM;
    float* out_cl = out_rl + 1;

    __nv_bfloat16 *xh, *xl, *rh, *rl, *cAh, *cAl, *cBh, *cBl, *Wh, *Wl, *Wth, *Wtl;
    cudaGetSymbolAddress((void**)&xh,  g_xh);  cudaGetSymbolAddress((void**)&xl,  g_xl);
    cudaGetSymbolAddress((void**)&rh,  g_rh);  cudaGetSymbolAddress((void**)&rl,  g_rl);
    cudaGetSymbolAddress((void**)&cAh, g_cAh); cudaGetSymbolAddress((void**)&cAl, g_cAl);
    cudaGetSymbolAddress((void**)&cBh, g_cBh); cudaGetSymbolAddress((void**)&cBl, g_cBl);
    cudaGetSymbolAddress((void**)&Wh,  g_Wh);  cudaGetSymbolAddress((void**)&Wl,  g_Wl);
    cudaGetSymbolAddress((void**)&Wth, g_Wth); cudaGetSymbolAddress((void**)&Wtl, g_Wtl);

    // Stage sizes: BM=128 -> 24KB * 3 = 72KB ; BM=64 -> 16KB * 3 = 48KB
    const int smem128 = 3 * (2 * 128 * 64 + 2 * 64 * 64);
    const int smem64  = 3 * (2 * 64 * 64 + 2 * 64 * 64);
    cudaFuncSetAttribute(fista_mma_kernel<128>,
                         cudaFuncAttributeMaxDynamicSharedMemorySize, smem128);
    cudaFuncSetAttribute(fista_mma_kernel<64>,
                         cudaFuncAttributeMaxDynamicSharedMemorySize, smem64);

    // FISTA momentum coefficients
    float al_[5] = {0, 0, 0, 0, 0}, be_[5] = {0, 0, 0, 0, 0};
    {
        double tp = (sqrt(5.0) + 1.0) / 2.0;
        for (int i = 2; i < 5; i++) {
            double tn = (sqrt(1.0 + 4.0 * tp * tp) + 1.0) / 2.0;
            al_[i] = (float)((tp + tn - 1.0) / tn);
            be_[i] = (float)((1.0 - tp) / tn);
            tp = tn;
        }
    }

    const dim3 blkStep(256), blkRes(128);
    const dim3 grdStep(DDIM / BN, NROWS / 128);  // (32, 128) BM=128
    const dim3 grdRes (CDIM / BN, NROWS / 64);   // (8, 256)  BM=64
    const int NCC = CDIM / BK;                   // 16 chunks (K=512)
    const int NCD = DDIM / BK;                   // 64 chunks (K=2048)

    prep_w_kernel<<<(DDIM * CDIM + 255) / 256, 256>>>(W);
    prep_x_kernel<<<(NROWS * CDIM + 255) / 256, 256>>>(x);
    zero_losses_kernel<<<1, 1>>>(out_rl, out_cl);

    // i=0: c = relu(0.1 * x@W^T - 0.01) -> cA
    fista_mma_kernel<128><<<grdStep, blkStep, smem128>>>(
        xh, xl, Wh, Wl, CDIM, NCC, DDIM, 0,
        nullptr, nullptr, nullptr, nullptr, 0.f, 0.f,
        cAh, cAl, nullptr, nullptr, nullptr, nullptr);

    // i=1: r = x - cA@W ; c = relu(cA + 0.1*r@W^T - 0.01) -> cB
    fista_mma_kernel<64><<<grdRes, blkRes, smem64>>>(
        cAh, cAl, Wth, Wtl, DDIM, NCD, CDIM, 1,
        nullptr, nullptr, nullptr, nullptr, 0.f, 0.f,
        rh, rl, nullptr, nullptr, x, nullptr);
    fista_mma_kernel<128><<<grdStep, blkStep, smem128>>>(
        rh, rl, Wh, Wl, CDIM, NCC, DDIM, 0,
        cAh, cAl, cAh, cAl, 1.f, 0.f,
        cBh, cBl, nullptr, nullptr, nullptr, nullptr);
    // state: c = cB, c_pre = cA

    // i=2
    fista_mma_kernel<64><<<grdRes, blkRes, smem64>>>(
        cBh, cBl, Wth, Wtl, DDIM, NCD, CDIM, 1,
        nullptr, nullptr, nullptr, nullptr, 0.f, 0.f,
        rh, rl, nullptr, nullptr, x, nullptr);
    fista_mma_kernel<128><<<grdStep, blkStep, smem128>>>(
        rh, rl, Wh, Wl, CDIM, NCC, DDIM, 0,
        cBh, cBl, cAh, cAl, al_[2], be_[2],
        cAh, cAl, nullptr, nullptr, nullptr, nullptr);
    // state: c = cA, c_pre = cB

    // i=3
    fista_mma_kernel<64><<<grdRes, blkRes, smem64>>>(
        cAh, cAl, Wth, Wtl, DDIM, NCD, CDIM, 1,
        nullptr, nullptr, nullptr, nullptr, 0.f, 0.f,
        rh, rl, nullptr, nullptr, x, nullptr);
    fista_mma_kernel<128><<<grdStep, blkStep, smem128>>>(
        rh, rl, Wh, Wl, CDIM, NCC, DDIM, 0,
        cAh, cAl, cBh, cBl, al_[3], be_[3],
        cBh, cBl, nullptr, nullptr, nullptr, nullptr);
    // state: c = cB, c_pre = cA

    // i=4: final step; write c fp32 to out_c, split planes to cA, + c_loss
    fista_mma_kernel<64><<<grdRes, blkRes, smem64>>>(
        cBh, cBl, Wth, Wtl, DDIM, NCD, CDIM, 1,
        nullptr, nullptr, nullptr, nullptr, 0.f, 0.f,
        rh, rl, nullptr, nullptr, x, nullptr);
    fista_mma_kernel<128><<<grdStep, blkStep, smem128>>>(
        rh, rl, Wh, Wl, CDIM, NCC, DDIM, 0,
        cBh, cBl, cAh, cAl, al_[4], be_[4],
        cAh, cAl, out_c, nullptr, nullptr, out_cl);

    // final reconstruction: xp = c@W, r = x - xp, r_loss
    fista_mma_kernel<64><<<grdRes, blkRes, smem64>>>(
        cAh, cAl, Wth, Wtl, DDIM, NCD, CDIM, 1,
        nullptr, nullptr, nullptr, nullptr, 0.f, 0.f,
        nullptr, nullptr, out_r, out_xp, x, out_rl);
}

// round 17
// speedup vs baseline: 1.0018x; 1.0018x over previous
#include <cuda_runtime.h>
#include <cuda_bf16.h>
#include <math.h>
#include <stdint.h>

#define NROWS 16384
#define CDIM  512
#define DDIM  2048

#define BN 64
#define BK 32                    // k elements per pipeline stage
#define STAGES 3

// Swizzled smem layout: two logical 64B rows per 128B physical row.
// phys(row, seg) = (row>>1)*128 + ((((row&1)<<2)|seg) ^ ((row>>1)&7))*16
// Conflict-free for cp.async 16B writes and ldmatrix m8n8 reads.
__device__ __forceinline__ uint32_t swz(int row, int seg) {
    return (uint32_t)((row >> 1) * 128 +
                      (((((row & 1) << 2) | seg) ^ ((row >> 1) & 7)) << 4));
}

// ---------------------------------------------------------------------------
// Static scratch (no allocation allowed). Activations stored as bf16 hi/lo
// plane pairs; value = hi + lo reconstructs fp32 to ~2^-18.
// ---------------------------------------------------------------------------
__device__ __nv_bfloat16 g_xh [(size_t)NROWS * CDIM], g_xl [(size_t)NROWS * CDIM];
__device__ __nv_bfloat16 g_rh [(size_t)NROWS * CDIM], g_rl [(size_t)NROWS * CDIM];
__device__ __nv_bfloat16 g_cAh[(size_t)NROWS * DDIM], g_cAl[(size_t)NROWS * DDIM];
__device__ __nv_bfloat16 g_cBh[(size_t)NROWS * DDIM], g_cBl[(size_t)NROWS * DDIM];
__device__ __nv_bfloat16 g_Wh [(size_t)DDIM * CDIM],  g_Wl [(size_t)DDIM * CDIM];
__device__ __nv_bfloat16 g_Wth[(size_t)CDIM * DDIM],  g_Wtl[(size_t)CDIM * DDIM];

// ---------------------------------------------------------------------------
// PTX helpers (family-common sm_80+: cp.async, mma.sync, ldmatrix)
// ---------------------------------------------------------------------------
__device__ __forceinline__ uint32_t smem_u32(const void* p) {
    return (uint32_t)__cvta_generic_to_shared(p);
}
__device__ __forceinline__ void cp16(uint32_t saddr, const void* gaddr) {
    asm volatile("cp.async.cg.shared.global [%0], [%1], 16;"
                 :: "r"(saddr), "l"(gaddr) : "memory");
}
__device__ __forceinline__ void cp_commit() {
    asm volatile("cp.async.commit_group;" ::: "memory");
}
#define CP_WAIT_GROUP(n) asm volatile("cp.async.wait_group %0;" :: "n"(n) : "memory")

__device__ __forceinline__ void ldsm_x4(uint32_t& r0, uint32_t& r1, uint32_t& r2,
                                        uint32_t& r3, uint32_t addr) {
    asm volatile("ldmatrix.sync.aligned.m8n8.x4.shared.b16 {%0,%1,%2,%3}, [%4];"
                 : "=r"(r0), "=r"(r1), "=r"(r2), "=r"(r3) : "r"(addr));
}
__device__ __forceinline__ void mma_bf16(float* c, const uint32_t* a,
                                         uint32_t b0, uint32_t b1) {
    asm("mma.sync.aligned.m16n8k16.row.col.f32.bf16.bf16.f32 "
        "{%0,%1,%2,%3}, {%4,%5,%6,%7}, {%8,%9}, {%0,%1,%2,%3};"
        : "+f"(c[0]), "+f"(c[1]), "+f"(c[2]), "+f"(c[3])
        : "r"(a[0]), "r"(a[1]), "r"(a[2]), "r"(a[3]), "r"(b0), "r"(b1));
}
__device__ __forceinline__ void split_bf16(float v, __nv_bfloat16& h, __nv_bfloat16& l) {
    h = __float2bfloat16(v);
    l = __float2bfloat16(v - __bfloat162float(h));
}

// ---------------------------------------------------------------------------
// Small kernels
// ---------------------------------------------------------------------------
__global__ void zero_losses_kernel(float* rl, float* cl) { *rl = 0.0f; *cl = 0.0f; }

__global__ void prep_w_kernel(const float* __restrict__ W) {
    int i = blockIdx.x * blockDim.x + threadIdx.x;
    if (i < DDIM * CDIM) {
        __nv_bfloat16 h, l;
        split_bf16(W[i], h, l);
        g_Wh[i] = h; g_Wl[i] = l;
        int d = i / CDIM, c = i % CDIM;
        g_Wth[(size_t)c * DDIM + d] = h;
        g_Wtl[(size_t)c * DDIM + d] = l;
    }
}
__global__ void prep_x_kernel(const float* __restrict__ X) {
    int i = blockIdx.x * blockDim.x + threadIdx.x;
    if (i < NROWS * CDIM) {
        __nv_bfloat16 h, l;
        split_bf16(X[i], h, l);
        g_xh[i] = h; g_xl[i] = l;
    }
}

// ---------------------------------------------------------------------------
// Unified bf16-split GEMM (mma.sync m16n8k16, 3-product hi/lo, ldmatrix,
// swizzled smem, 3-stage cp.async pipeline), templated on BM:
//   BM=128: 256 thr, 4x2 warps (step GEMM, big grid)
//   BM=64 : 128 thr, 2x2 warps (residual GEMM: 2x grid -> less wave-tail waste)
// + fused FISTA epilogue.  D = (Ah+Al)[NROWS x K] @ (Bh+Bl)[Ntot x K]^T
// ---------------------------------------------------------------------------
template <int BM_>
__global__ __launch_bounds__(BM_ * 2, 768 / (BM_ * 2))
void fista_mma_kernel(const __nv_bfloat16* __restrict__ Ah, const __nv_bfloat16* __restrict__ Al,
                      const __nv_bfloat16* __restrict__ Bh, const __nv_bfloat16* __restrict__ Bl,
                      int K, int nChunks, int Ntot, int mode,
                      const __nv_bfloat16* __restrict__ cInH, const __nv_bfloat16* __restrict__ cInL,
                      const __nv_bfloat16* __restrict__ cPreH, const __nv_bfloat16* __restrict__ cPreL,
                      float alpha, float beta,
                      __nv_bfloat16* __restrict__ outH, __nv_bfloat16* __restrict__ outL,
                      float* __restrict__ outF, float* __restrict__ out2,
                      const float* __restrict__ Xres, float* __restrict__ loss)
{
    constexpr int THREADS = BM_ * 2;
    constexpr int NWM = BM_ / 32;                      // warps along M
    constexpr int A_TILE = BM_ * 64;                   // bytes per A plane
    constexpr int B_TILE = 64 * 64;                    // bytes per B plane
    constexpr int STAGE_BYTES = 2 * A_TILE + 2 * B_TILE;

    extern __shared__ char dyn_smem[];
    __shared__ float s_red[THREADS];

    const int tid = threadIdx.x;
    const int lane = tid & 31, wid = tid >> 5;
    const int gq = lane >> 2, tig = lane & 3;
    const int warpM = wid % NWM, warpN = wid / NWM;    // NWM x 2 warps, 32x32 each
    const int rowBase = blockIdx.y * BM_;
    const int colBase = blockIdx.x * BN;
    const uint32_t sBase = smem_u32(dyn_smem);

    // Per-lane ldmatrix swizzled offsets (XOR term invariant under +16-row steps).
    const int aRowL = (lane & 7) + ((lane >> 3) & 1) * 8;
    const int aSegSel = (lane >> 4) & 1;
    const uint32_t aOff0 = swz(aRowL, 0 + aSegSel);     // ks=0: segs {0,1}
    const uint32_t aOff1 = swz(aRowL, 2 + aSegSel);     // ks=1: segs {2,3}
    const int bRowL = (lane & 7) + ((lane >> 4) & 1) * 8;
    const int bSegSel = (lane >> 3) & 1;
    const uint32_t bOff0 = swz(bRowL, 0 + bSegSel);
    const uint32_t bOff1 = swz(bRowL, 2 + bSegSel);

    float acc[2][4][4];                                 // [mi][ni(n8)][frag]
    #pragma unroll
    for (int mi = 0; mi < 2; mi++)
        #pragma unroll
        for (int ni = 0; ni < 4; ni++)
            #pragma unroll
            for (int q = 0; q < 4; q++) acc[mi][ni][q] = 0.0f;

    // ---- stage loader ----
    auto load_stage = [&](int t) {
        const uint32_t stB = sBase + (t % STAGES) * STAGE_BYTES;
        const int k0 = t * BK;
        #pragma unroll
        for (int p = 0; p < 2; p++) {                   // A planes: BM_*4 slots
            const __nv_bfloat16* base = p ? Al : Ah;
            #pragma unroll
            for (int i = 0; i < (BM_ * 4) / THREADS; i++) {
                int slot = tid + i * THREADS;
                int row = slot >> 2, seg = slot & 3;
                cp16(stB + p * A_TILE + swz(row, seg),
                     base + (size_t)(rowBase + row) * K + k0 + seg * 8);
            }
        }
        #pragma unroll
        for (int p = 0; p < 2; p++) {                   // B planes: 256 slots
            const __nv_bfloat16* base = p ? Bl : Bh;
            #pragma unroll
            for (int i = 0; i < 256 / THREADS; i++) {
                int slot = tid + i * THREADS;
                int row = slot >> 2, seg = slot & 3;
                cp16(stB + 2 * A_TILE + p * B_TILE + swz(row, seg),
                     base + (size_t)(colBase + row) * K + k0 + seg * 8);
            }
        }
    };

    // ---- prologue: two stages in flight ----
    load_stage(0); cp_commit();
    load_stage(1); cp_commit();

    // ---- mainloop ----
    for (int t = 0; t < nChunks; t++) {
        CP_WAIT_GROUP(1);                               // chunk t resident; t+1 may fly
        __syncthreads();
        const int pf = t + 2;
        if (pf < nChunks) load_stage(pf);
        cp_commit();

        const uint32_t stB = sBase + (t % STAGES) * STAGE_BYTES;
        const uint32_t aH = stB + (uint32_t)warpM * 2048;            // 32 rows = 2048B
        const uint32_t aL = aH + A_TILE;
        const uint32_t bH = stB + 2 * A_TILE + (uint32_t)warpN * 2048;
        const uint32_t bL = bH + B_TILE;

        #pragma unroll
        for (int ks = 0; ks < 2; ks++) {                // two k16 steps per BK=32
            const uint32_t aOff = ks ? aOff1 : aOff0;
            const uint32_t bOff = ks ? bOff1 : bOff0;
            uint32_t ah[2][4], al[2][4];
            #pragma unroll
            for (int mi = 0; mi < 2; mi++) {
                ldsm_x4(ah[mi][0], ah[mi][1], ah[mi][2], ah[mi][3], aH + aOff + mi * 1024);
                ldsm_x4(al[mi][0], al[mi][1], al[mi][2], al[mi][3], aL + aOff + mi * 1024);
            }
            #pragma unroll
            for (int np = 0; np < 2; np++) {            // n8 pair {2np, 2np+1}
                uint32_t bh0, bh1, bh2, bh3, bl0, bl1, bl2, bl3;
                ldsm_x4(bh0, bh1, bh2, bh3, bH + bOff + np * 1024);
                ldsm_x4(bl0, bl1, bl2, bl3, bL + bOff + np * 1024);
                #pragma unroll
                for (int mi = 0; mi < 2; mi++) {
                    mma_bf16(acc[mi][2 * np],     ah[mi], bh0, bh1);   // hi*hi
                    mma_bf16(acc[mi][2 * np],     ah[mi], bl0, bl1);   // hi*lo
                    mma_bf16(acc[mi][2 * np],     al[mi], bh0, bh1);   // lo*hi
                    mma_bf16(acc[mi][2 * np + 1], ah[mi], bh2, bh3);
                    mma_bf16(acc[mi][2 * np + 1], ah[mi], bl2, bl3);
                    mma_bf16(acc[mi][2 * np + 1], al[mi], bh2, bh3);
                }
            }
        }
    }

    // ---- fused epilogue ----
    float lsum = 0.0f;
    #pragma unroll
    for (int mi = 0; mi < 2; mi++) {
        #pragma unroll
        for (int ni = 0; ni < 4; ni++) {
            const int col = colBase + warpN * 32 + ni * 8 + 2 * tig;
            #pragma unroll
            for (int half = 0; half < 2; half++) {
                const int row = rowBase + warpM * 32 + mi * 16 + gq + half * 8;
                const float v0 = acc[mi][ni][half * 2 + 0];
                const float v1 = acc[mi][ni][half * 2 + 1];
                const size_t off = (size_t)row * Ntot + col;

                if (mode == 0) {
                    float w0 = fmaf(0.1f, v0, -0.01f);
                    float w1 = fmaf(0.1f, v1, -0.01f);
                    if (cInH) {
                        __nv_bfloat162 ch = *(const __nv_bfloat162*)(cInH + off);
                        __nv_bfloat162 cl = *(const __nv_bfloat162*)(cInL + off);
                        w0 = fmaf(alpha, __bfloat162float(ch.x) + __bfloat162float(cl.x), w0);
                        w1 = fmaf(alpha, __bfloat162float(ch.y) + __bfloat162float(cl.y), w1);
                        if (beta != 0.0f) {
                            __nv_bfloat162 ph = *(const __nv_bfloat162*)(cPreH + off);
                            __nv_bfloat162 pl = *(const __nv_bfloat162*)(cPreL + off);
                            w0 = fmaf(beta, __bfloat162float(ph.x) + __bfloat162float(pl.x), w0);
                            w1 = fmaf(beta, __bfloat162float(ph.y) + __bfloat162float(pl.y), w1);
                        }
                    }
                    w0 = fmaxf(w0, 0.0f);
                    w1 = fmaxf(w1, 0.0f);
                    lsum += w0 + w1;
                    __nv_bfloat16 h0, l0, h1, l1;
                    split_bf16(w0, h0, l0);
                    split_bf16(w1, h1, l1);
                    *(__nv_bfloat162*)(outH + off) = __nv_bfloat162(h0, h1);
                    *(__nv_bfloat162*)(outL + off) = __nv_bfloat162(l0, l1);
                    if (outF) *(float2*)(outF + off) = make_float2(w0, w1);
                } else {
                    float2 xv = *(const float2*)(Xres + off);
                    float r0 = xv.x - v0, r1 = xv.y - v1;
                    lsum = fmaf(r0, r0, fmaf(r1, r1, lsum));
                    if (outH) {
                        __nv_bfloat16 h0, l0, h1, l1;
                        split_bf16(r0, h0, l0);
                        split_bf16(r1, h1, l1);
                        *(__nv_bfloat162*)(outH + off) = __nv_bfloat162(h0, h1);
                        *(__nv_bfloat162*)(outL + off) = __nv_bfloat162(l0, l1);
                    }
                    if (out2) *(float2*)(out2 + off) = make_float2(v0, v1);
                    if (outF) *(float2*)(outF + off) = make_float2(r0, r1);
                }
            }
        }
    }

    if (loss) {
        s_red[tid] = lsum;
        __syncthreads();
        #pragma unroll
        for (int s = THREADS / 2; s > 0; s >>= 1) {
            if (tid < s) s_red[tid] += s_red[tid + s];
            __syncthreads();
        }
        if (tid == 0) atomicAdd(loss, (mode == 0 ? 0.1f : 1.0f) * s_red[0]);
    }
}

// ---------------------------------------------------------------------------
extern "C" void kernel_launch(void* const* d_in, const int* in_sizes, int n_in,
                              void* d_out, int out_size)
{
    (void)in_sizes; (void)n_in; (void)out_size;
    const float* x = (const float*)d_in[0];       // [16384, 512]
    const float* W = (const float*)d_in[1];       // [2048, 512]

    float* out    = (float*)d_out;
    float* out_c  = out;
    float* out_xp = out_c  + (size_t)NROWS * DDIM;
    float* out_r  = out_xp + (size_t)NROWS * CDIM;
    float* out_rl = out_r  + (size_t)NROWS * CDIM;
    float* out_cl = out_rl + 1;

    __nv_bfloat16 *xh, *xl, *rh, *rl, *cAh, *cAl, *cBh, *cBl, *Wh, *Wl, *Wth, *Wtl;
    cudaGetSymbolAddress((void**)&xh,  g_xh);  cudaGetSymbolAddress((void**)&xl,  g_xl);
    cudaGetSymbolAddress((void**)&rh,  g_rh);  cudaGetSymbolAddress((void**)&rl,  g_rl);
    cudaGetSymbolAddress((void**)&cAh, g_cAh); cudaGetSymbolAddress((void**)&cAl, g_cAl);
    cudaGetSymbolAddress((void**)&cBh, g_cBh); cudaGetSymbolAddress((void**)&cBl, g_cBl);
    cudaGetSymbolAddress((void**)&Wh,  g_Wh);  cudaGetSymbolAddress((void**)&Wl,  g_Wl);
    cudaGetSymbolAddress((void**)&Wth, g_Wth); cudaGetSymbolAddress((void**)&Wtl, g_Wtl);

    // Stage sizes: BM=128 -> 24KB * 3 = 72KB ; BM=64 -> 16KB * 3 = 48KB
    const int smem128 = 3 * (2 * 128 * 64 + 2 * 64 * 64);
    const int smem64  = 3 * (2 * 64 * 64 + 2 * 64 * 64);
    cudaFuncSetAttribute(fista_mma_kernel<128>,
                         cudaFuncAttributeMaxDynamicSharedMemorySize, smem128);
    cudaFuncSetAttribute(fista_mma_kernel<64>,
                         cudaFuncAttributeMaxDynamicSharedMemorySize, smem64);

    // FISTA momentum coefficients
    float al_[5] = {0, 0, 0, 0, 0}, be_[5] = {0, 0, 0, 0, 0};
    {
        double tp = (sqrt(5.0) + 1.0) / 2.0;
        for (int i = 2; i < 5; i++) {
            double tn = (sqrt(1.0 + 4.0 * tp * tp) + 1.0) / 2.0;
            al_[i] = (float)((tp + tn - 1.0) / tn);
            be_[i] = (float)((1.0 - tp) / tn);
            tp = tn;
        }
    }

    const dim3 blkStep(256), blkRes(128);
    const dim3 grdStep(DDIM / BN, NROWS / 128);  // (32, 128) BM=128
    const dim3 grdRes (CDIM / BN, NROWS / 64);   // (8, 256)  BM=64
    const int NCC = CDIM / BK;                   // 16 chunks (K=512)
    const int NCD = DDIM / BK;                   // 64 chunks (K=2048)

    prep_w_kernel<<<(DDIM * CDIM + 255) / 256, 256>>>(W);
    prep_x_kernel<<<(NROWS * CDIM + 255) / 256, 256>>>(x);
    zero_losses_kernel<<<1, 1>>>(out_rl, out_cl);

    // i=0: c = relu(0.1 * x@W^T - 0.01) -> cA
    fista_mma_kernel<128><<<grdStep, blkStep, smem128>>>(
        xh, xl, Wh, Wl, CDIM, NCC, DDIM, 0,
        nullptr, nullptr, nullptr, nullptr, 0.f, 0.f,
        cAh, cAl, nullptr, nullptr, nullptr, nullptr);

    // i=1: r = x - cA@W ; c = relu(cA + 0.1*r@W^T - 0.01) -> cB
    fista_mma_kernel<64><<<grdRes, blkRes, smem64>>>(
        cAh, cAl, Wth, Wtl, DDIM, NCD, CDIM, 1,
        nullptr, nullptr, nullptr, nullptr, 0.f, 0.f,
        rh, rl, nullptr, nullptr, x, nullptr);
    fista_mma_kernel<128><<<grdStep, blkStep, smem128>>>(
        rh, rl, Wh, Wl, CDIM, NCC, DDIM, 0,
        cAh, cAl, cAh, cAl, 1.f, 0.f,
        cBh, cBl, nullptr, nullptr, nullptr, nullptr);
    // state: c = cB, c_pre = cA

    // i=2
    fista_mma_kernel<64><<<grdRes, blkRes, smem64>>>(
        cBh, cBl, Wth, Wtl, DDIM, NCD, CDIM, 1,
        nullptr, nullptr, nullptr, nullptr, 0.f, 0.f,
        rh, rl, nullptr, nullptr, x, nullptr);
    fista_mma_kernel<128><<<grdStep, blkStep, smem128>>>(
        rh, rl, Wh, Wl, CDIM, NCC, DDIM, 0,
        cBh, cBl, cAh, cAl, al_[2], be_[2],
        cAh, cAl, nullptr, nullptr, nullptr, nullptr);
    // state: c = cA, c_pre = cB

    // i=3
    fista_mma_kernel<64><<<grdRes, blkRes, smem64>>>(
        cAh, cAl, Wth, Wtl, DDIM, NCD, CDIM, 1,
        nullptr, nullptr, nullptr, nullptr, 0.f, 0.f,
        rh, rl, nullptr, nullptr, x, nullptr);
    fista_mma_kernel<128><<<grdStep, blkStep, smem128>>>(
        rh, rl, Wh, Wl, CDIM, NCC, DDIM, 0,
        cAh, cAl, cBh, cBl, al_[3], be_[3],
        cBh, cBl, nullptr, nullptr, nullptr, nullptr);
    // state: c = cB, c_pre = cA

    // i=4: final step; write c fp32 to out_c, split planes to cA, + c_loss
    fista_mma_kernel<64><<<grdRes, blkRes, smem64>>>(
        cBh, cBl, Wth, Wtl, DDIM, NCD, CDIM, 1,
        nullptr, nullptr, nullptr, nullptr, 0.f, 0.f,
        rh, rl, nullptr, nullptr, x, nullptr);
    fista_mma_kernel<128><<<grdStep, blkStep, smem128>>>(
        rh, rl, Wh, Wl, CDIM, NCC, DDIM, 0,
        cBh, cBl, cAh, cAl, al_[4], be_[4],
        cAh, cAl, out_c, nullptr, nullptr, out_cl);

    // final reconstruction: xp = c@W, r = x - xp, r_loss
    fista_mma_kernel<64><<<grdRes, blkRes, smem64>>>(
        cAh, cAl, Wth, Wtl, DDIM, NCD, CDIM, 1,
        nullptr, nullptr, nullptr, nullptr, 0.f, 0.f,
        nullptr, nullptr, out_r, out_xp, x, out_rl);
}